// round 11
// baseline (speedup 1.0000x reference)
#include <cuda_runtime.h>
#include <cstdint>

// Scratch: split-K partials [16][512*256] (8 MB) and x3 [512 x 64].
static __device__ float g_part[16][512 * 256];
static __device__ float g_x3[512 * 64];

// ---------------------------------------------------------------------------
// Kernel A1: split-K partial GEMM.  part[z] = x[32r x 32k] @ w2^T[32k x 64h]
// grid (16, 4, 16) = 1024 blocks, 128 threads, all resident.  [R8 form]
// ---------------------------------------------------------------------------
__global__ void __launch_bounds__(128) gemm1_part_kernel(
    const float* __restrict__ x,    // [512, 512]
    const float* __restrict__ w2)   // [256, 512]
{
    __shared__ float xs[32][36];
    __shared__ float ws[64][36];

    const int t  = threadIdx.x;
    const int r0 = blockIdx.x * 32;
    const int h0 = blockIdx.y * 64;
    const int k0 = blockIdx.z * 32;

    #pragma unroll
    for (int i = 0; i < 2; ++i) {
        const int idx = t + i * 128;
        const int r   = idx >> 3;
        const int kq  = (idx & 7) * 4;
        float4 v = *reinterpret_cast<const float4*>(
            x + (size_t)(r0 + r) * 512 + k0 + kq);
        *reinterpret_cast<float4*>(&xs[r][kq]) = v;
    }
    #pragma unroll
    for (int i = 0; i < 4; ++i) {
        const int idx = t + i * 128;
        const int r   = idx >> 3;
        const int kq  = (idx & 7) * 4;
        float4 v = *reinterpret_cast<const float4*>(
            w2 + (size_t)(h0 + r) * 512 + k0 + kq);
        *reinterpret_cast<float4*>(&ws[r][kq]) = v;
    }

    float acc[4][4];
    #pragma unroll
    for (int i = 0; i < 4; ++i)
        #pragma unroll
        for (int j = 0; j < 4; ++j) acc[i][j] = 0.f;

    const int tx = t & 15;
    const int ty = t >> 4;

    __syncthreads();

    #pragma unroll
    for (int kq = 0; kq < 32; kq += 4) {
        float4 a[4], bv[4];
        #pragma unroll
        for (int i = 0; i < 4; ++i)
            a[i] = *reinterpret_cast<const float4*>(&xs[ty + 8 * i][kq]);
        #pragma unroll
        for (int j = 0; j < 4; ++j)
            bv[j] = *reinterpret_cast<const float4*>(&ws[tx + 16 * j][kq]);
        #pragma unroll
        for (int i = 0; i < 4; ++i)
            #pragma unroll
            for (int j = 0; j < 4; ++j) {
                acc[i][j] = fmaf(a[i].x, bv[j].x, acc[i][j]);
                acc[i][j] = fmaf(a[i].y, bv[j].y, acc[i][j]);
                acc[i][j] = fmaf(a[i].z, bv[j].z, acc[i][j]);
                acc[i][j] = fmaf(a[i].w, bv[j].w, acc[i][j]);
            }
    }

    float* dst = g_part[blockIdx.z];
    #pragma unroll
    for (int i = 0; i < 4; ++i)
        #pragma unroll
        for (int j = 0; j < 4; ++j)
            dst[(size_t)(r0 + ty + 8 * i) * 256 + h0 + tx + 16 * j] = acc[i][j];
}

// ---------------------------------------------------------------------------
// Kernel A2: reduce 16 partials + bias + LeakyReLU, GEMM2 with w3 staged
// through smem, + softmaxes -> x3.  8 rows/block, 256 threads, grid 64.
// ---------------------------------------------------------------------------
__global__ void __launch_bounds__(256) head_kernel(
    const float* __restrict__ b2,   // [256]
    const float* __restrict__ w3,   // [55, 256]
    const float* __restrict__ b3)   // [55]
{
    __shared__ float hs[8][260];
    __shared__ float ws[55][68];
    __shared__ float zs[8][60];

    const int t  = threadIdx.x;
    const int r0 = blockIdx.x * 8;

    const float bb = b2[t];
    #pragma unroll
    for (int i = 0; i < 8; ++i) {
        const size_t off = (size_t)(r0 + i) * 256 + t;
        float s = bb;
        #pragma unroll
        for (int z = 0; z < 16; ++z) s += g_part[z][off];
        hs[i][t] = (s >= 0.f) ? s : 0.01f * s;
    }

    const int o0 = t;
    const int o1 = t + 256;
    const int r0o = o0 & 7, c0o = o0 >> 3;
    const int r1o = o1 & 7, c1o = o1 >> 3;
    float acc0 = 0.f, acc1 = 0.f;

    #pragma unroll
    for (int chunk = 0; chunk < 4; ++chunk) {
        __syncthreads();
        for (int idx = t; idx < 880; idx += 256) {
            const int c = idx >> 4;
            const int j = (idx & 15) * 4;
            float4 v = *reinterpret_cast<const float4*>(
                w3 + (size_t)c * 256 + chunk * 64 + j);
            *reinterpret_cast<float4*>(&ws[c][j]) = v;
        }
        __syncthreads();

        #pragma unroll 4
        for (int k = 0; k < 16; ++k) {
            const int kj = k * 4;
            {
                const float4 a = *reinterpret_cast<const float4*>(
                    &hs[r0o][chunk * 64 + kj]);
                const float4 w = *reinterpret_cast<const float4*>(&ws[c0o][kj]);
                acc0 = fmaf(a.x, w.x, acc0); acc0 = fmaf(a.y, w.y, acc0);
                acc0 = fmaf(a.z, w.z, acc0); acc0 = fmaf(a.w, w.w, acc0);
            }
            if (o1 < 440) {
                const float4 a = *reinterpret_cast<const float4*>(
                    &hs[r1o][chunk * 64 + kj]);
                const float4 w = *reinterpret_cast<const float4*>(&ws[c1o][kj]);
                acc1 = fmaf(a.x, w.x, acc1); acc1 = fmaf(a.y, w.y, acc1);
                acc1 = fmaf(a.z, w.z, acc1); acc1 = fmaf(a.w, w.w, acc1);
            }
        }
    }
    zs[r0o][c0o] = acc0 + b3[c0o];
    if (o1 < 440) zs[r1o][c1o] = acc1 + b3[c1o];
    __syncthreads();

    if (t < 48) {
        const int r     = t / 6;
        const int g     = t - 6 * r;
        const int start = (g == 0) ? 0 : 5 + 10 * (g - 1);
        const int len   = (g == 0) ? 5 : 10;
        float m = -3.0e38f;
        for (int c = 0; c < len; ++c) m = fmaxf(m, zs[r][start + c]);
        float s = 0.f;
        for (int c = 0; c < len; ++c) s += __expf(zs[r][start + c] - m);
        const float inv = 1.0f / s;
        float* dst = &g_x3[(size_t)(r0 + r) * 64];
        for (int c = 0; c < len; ++c)
            dst[start + c] = __expf(zs[r][start + c] - m) * inv;
    }
}

// ---------------------------------------------------------------------------
// Kernel B: expansion via SMEM staging + TMA bulk store.
//
// grid (8, 512), 640 threads, dynamic smem:
//   buf[12800]  staged output chunk (51200 B)
//   sv[1284]    run values
//   p[64]       probability row
//
// Block bx covers floats [pad + 12800*bx, ...) of row b (pad = b & 3).
// Phase 2 writes float4s to SMEM (STS.128, issue ~1cyc) using the same
// loop-invariant run-phase trick (iteration stride 2560 == 0 mod 10), then
// ONE cp.async.bulk (SMEM->GMEM) moves the whole chunk — no per-warp STG
// issue cost. bx<7: 51200 B; bx==7: 41584 B (10396 floats). Head/tail
// scalars via direct STG.
// ---------------------------------------------------------------------------
__global__ void __launch_bounds__(640) expand_kernel(float* __restrict__ out)
{
    extern __shared__ float dsm[];
    float* buf = dsm;            // [12800]
    float* sv  = dsm + 12800;    // [1284]
    float* p   = dsm + 14084;    // [64]

    const unsigned t   = threadIdx.x;
    const unsigned bx  = blockIdx.x;
    const unsigned b   = blockIdx.y;
    const unsigned pad = b & 3u;
    const unsigned rbase = bx * 1280u;   // multiple of 10

    if (t < 64u) p[t] = g_x3[(size_t)b * 64u + t];
    __syncthreads();

    // --- phase 1: run values for runs [rbase, rbase + 1282) ---
    #pragma unroll
    for (unsigned kk = 0; kk < 3u; ++kk) {
        const unsigned ri = t + kk * 640u;
        if (ri < 1282u) {
            const unsigned r = rbase + ri;
            float v = 0.f;
            if (r < 10000u) {
                if (r == 0u) {
                    v = p[0];
                } else if (r < 10u) {
                    v = p[1] * p[5 + r];
                } else if (r < 100u) {
                    const unsigned q1 = r / 10u;
                    v = p[2] * p[5 + q1] * p[15 + (r - 10u * q1)];
                } else if (r < 1000u) {
                    const unsigned q1 = r / 10u, q2 = r / 100u;
                    v = p[3] * p[5 + q2] * p[15 + (q1 - 10u * q2)]
                             * p[25 + (r - 10u * q1)];
                } else {
                    const unsigned q1 = r / 10u, q2 = r / 100u, q3 = r / 1000u;
                    v = p[4] * p[5 + q3] * p[15 + (q2 - 10u * q3)]
                             * p[25 + (q1 - 10u * q2)] * p[35 + (r - 10u * q1)];
                }
            }
            sv[ri] = v;
        }
    }
    __syncthreads();

    // --- phase 2: expand into SMEM buffer (STS.128) ---
    // buffer float index fi = 4*(t + 640k); global i = pad + 12800*bx + fi.
    // run-phase of (pad + 4t) is invariant across k (stride 2560 == 0 mod 10).
    const unsigned ph  = pad + 4u * t;       // < 2563
    const unsigned rt  = ph / 10u;
    const unsigned rem = ph - 10u * rt;
    const bool c1 = (rem + 1u < 10u);
    const bool c2 = (rem + 2u < 10u);
    const bool c3 = (rem + 3u < 10u);

    float4* bufv = reinterpret_cast<float4*>(buf);
    const unsigned nF4 = (bx < 7u) ? 3200u : 2599u;   // f4 count in this chunk
    #pragma unroll
    for (unsigned k = 0; k < 5u; ++k) {
        const unsigned vi = t + k * 640u;
        if (vi < nF4) {
            const unsigned ri = rt + k * 256u;
            const float f0 = sv[ri];
            const float f1 = sv[ri + 1u];
            float4 w;
            w.x = f0;
            w.y = c1 ? f0 : f1;
            w.z = c2 ? f0 : f1;
            w.w = c3 ? f0 : f1;
            bufv[vi] = w;
        }
    }
    // patch buf[0] (global i == 0) for pad==0 rows
    if (bx == 0u && pad == 0u && t == 0u) buf[0] = p[1] * p[5];
    __syncthreads();

    float* o = out + (size_t)b * 99999u;

    // --- phase 3: one TMA bulk store per block ---
    if (t == 0u) {
        asm volatile("fence.proxy.async.shared::cta;" ::: "memory");
        const unsigned nbytes = nF4 * 16u;
        float* gdst = o + pad + 12800u * bx;
        uint32_t saddr = (uint32_t)__cvta_generic_to_shared(buf);
        asm volatile(
            "cp.async.bulk.global.shared::cta.bulk_group [%0], [%1], %2;"
            :: "l"(gdst), "r"(saddr), "r"(nbytes) : "memory");
        asm volatile("cp.async.bulk.commit_group;" ::: "memory");
    }

    // --- head / tail scalars (direct STG, tiny) ---
    if (bx == 0u && pad != 0u && t < pad) {
        o[t] = (t == 0u) ? p[1] * p[5] : p[0];
    }
    if (bx == 7u && t < 3u - pad) {
        // i in [pad + 99996, 99999): run 9999 = rbase + 1039
        o[pad + 99996u + t] = sv[1039];
    }

    // wait for the bulk store's SMEM read before block teardown
    if (t == 0u) {
        asm volatile("cp.async.bulk.wait_group 0;" ::: "memory");
    }
}

// ---------------------------------------------------------------------------
extern "C" void kernel_launch(void* const* d_in, const int* in_sizes, int n_in,
                              void* d_out, int out_size)
{
    (void)in_sizes; (void)n_in; (void)out_size;
    const float* x  = (const float*)d_in[0];   // [512, 512]
    const float* w2 = (const float*)d_in[1];   // [256, 512]
    const float* b2 = (const float*)d_in[2];   // [256]
    const float* w3 = (const float*)d_in[3];   // [55, 256]
    const float* b3 = (const float*)d_in[4];   // [55]
    float* out = (float*)d_out;                // [512, 99999]

    const int dsm_bytes = (12800 + 1284 + 64) * 4;   // 56592
    cudaFuncSetAttribute(expand_kernel,
                         cudaFuncAttributeMaxDynamicSharedMemorySize, dsm_bytes);

    gemm1_part_kernel<<<dim3(16, 4, 16), 128>>>(x, w2);
    head_kernel<<<64, 256>>>(b2, w3, b3);
    expand_kernel<<<dim3(8, 512), 640, dsm_bytes>>>(out);
}

// round 12
// speedup vs baseline: 1.0780x; 1.0780x over previous
#include <cuda_runtime.h>

// Scratch: split-K partials [16][512*256] (8 MB) and x3 [512 x 64].
static __device__ float g_part[16][512 * 256];
static __device__ float g_x3[512 * 64];

// ---------------------------------------------------------------------------
// Kernel A1: split-K partial GEMM.  part[z] = x[64r x 32k] @ w2^T[32k x 64h]
// grid (8, 4, 16) = 512 blocks, 128 threads, all resident (~14 warps/SM).
// 8x4 register tiles: 12 LDS.128 per 4-k step feed 128 FFMA (ratio 10.7:1),
// so the smem crossbar (4 cyc/LDS.128/SM) is no longer co-binding with FMA.
// Rows strided 8, cols strided 16 (conflict-free LDS.128: 36-float rows).
// ---------------------------------------------------------------------------
__global__ void __launch_bounds__(128) gemm1_part_kernel(
    const float* __restrict__ x,    // [512, 512]
    const float* __restrict__ w2)   // [256, 512]
{
    __shared__ float xs[64][36];
    __shared__ float ws[64][36];

    const int t  = threadIdx.x;
    const int r0 = blockIdx.x * 64;
    const int h0 = blockIdx.y * 64;
    const int k0 = blockIdx.z * 32;

    // load x tile: 64 rows x 32 k = 512 float4 (4 per thread), coalesced
    #pragma unroll
    for (int i = 0; i < 4; ++i) {
        const int idx = t + i * 128;
        const int r   = idx >> 3;          // 0..63
        const int kq  = (idx & 7) * 4;     // 0..28
        float4 v = *reinterpret_cast<const float4*>(
            x + (size_t)(r0 + r) * 512 + k0 + kq);
        *reinterpret_cast<float4*>(&xs[r][kq]) = v;
    }
    // load w2 tile: 64 rows x 32 k = 512 float4 (4 per thread), coalesced
    #pragma unroll
    for (int i = 0; i < 4; ++i) {
        const int idx = t + i * 128;
        const int r   = idx >> 3;
        const int kq  = (idx & 7) * 4;
        float4 v = *reinterpret_cast<const float4*>(
            w2 + (size_t)(h0 + r) * 512 + k0 + kq);
        *reinterpret_cast<float4*>(&ws[r][kq]) = v;
    }

    float acc[8][4];
    #pragma unroll
    for (int i = 0; i < 8; ++i)
        #pragma unroll
        for (int j = 0; j < 4; ++j) acc[i][j] = 0.f;

    const int tx = t & 15;   // cols tx, tx+16, tx+32, tx+48
    const int ty = t >> 4;   // rows ty, ty+8, ..., ty+56

    __syncthreads();

    #pragma unroll
    for (int kq = 0; kq < 32; kq += 4) {
        float4 a[8], bv[4];
        #pragma unroll
        for (int i = 0; i < 8; ++i)
            a[i] = *reinterpret_cast<const float4*>(&xs[ty + 8 * i][kq]);
        #pragma unroll
        for (int j = 0; j < 4; ++j)
            bv[j] = *reinterpret_cast<const float4*>(&ws[tx + 16 * j][kq]);
        #pragma unroll
        for (int i = 0; i < 8; ++i)
            #pragma unroll
            for (int j = 0; j < 4; ++j) {
                acc[i][j] = fmaf(a[i].x, bv[j].x, acc[i][j]);
                acc[i][j] = fmaf(a[i].y, bv[j].y, acc[i][j]);
                acc[i][j] = fmaf(a[i].z, bv[j].z, acc[i][j]);
                acc[i][j] = fmaf(a[i].w, bv[j].w, acc[i][j]);
            }
    }

    float* dst = g_part[blockIdx.z];
    #pragma unroll
    for (int i = 0; i < 8; ++i)
        #pragma unroll
        for (int j = 0; j < 4; ++j)
            dst[(size_t)(r0 + ty + 8 * i) * 256 + h0 + tx + 16 * j] = acc[i][j];
}

// ---------------------------------------------------------------------------
// Kernel A2: reduce 16 partials + bias + LeakyReLU, GEMM2 with w3 staged
// through smem, + softmaxes -> x3.  8 rows/block, 256 threads, grid 64.
// ---------------------------------------------------------------------------
__global__ void __launch_bounds__(256) head_kernel(
    const float* __restrict__ b2,   // [256]
    const float* __restrict__ w3,   // [55, 256]
    const float* __restrict__ b3)   // [55]
{
    __shared__ float hs[8][260];
    __shared__ float ws[55][68];
    __shared__ float zs[8][60];

    const int t  = threadIdx.x;
    const int r0 = blockIdx.x * 8;

    const float bb = b2[t];
    #pragma unroll
    for (int i = 0; i < 8; ++i) {
        const size_t off = (size_t)(r0 + i) * 256 + t;
        float s = bb;
        #pragma unroll
        for (int z = 0; z < 16; ++z) s += g_part[z][off];
        hs[i][t] = (s >= 0.f) ? s : 0.01f * s;
    }

    const int o0 = t;
    const int o1 = t + 256;
    const int r0o = o0 & 7, c0o = o0 >> 3;
    const int r1o = o1 & 7, c1o = o1 >> 3;
    float acc0 = 0.f, acc1 = 0.f;

    #pragma unroll
    for (int chunk = 0; chunk < 4; ++chunk) {
        __syncthreads();
        for (int idx = t; idx < 880; idx += 256) {
            const int c = idx >> 4;
            const int j = (idx & 15) * 4;
            float4 v = *reinterpret_cast<const float4*>(
                w3 + (size_t)c * 256 + chunk * 64 + j);
            *reinterpret_cast<float4*>(&ws[c][j]) = v;
        }
        __syncthreads();

        #pragma unroll 4
        for (int k = 0; k < 16; ++k) {
            const int kj = k * 4;
            {
                const float4 a = *reinterpret_cast<const float4*>(
                    &hs[r0o][chunk * 64 + kj]);
                const float4 w = *reinterpret_cast<const float4*>(&ws[c0o][kj]);
                acc0 = fmaf(a.x, w.x, acc0); acc0 = fmaf(a.y, w.y, acc0);
                acc0 = fmaf(a.z, w.z, acc0); acc0 = fmaf(a.w, w.w, acc0);
            }
            if (o1 < 440) {
                const float4 a = *reinterpret_cast<const float4*>(
                    &hs[r1o][chunk * 64 + kj]);
                const float4 w = *reinterpret_cast<const float4*>(&ws[c1o][kj]);
                acc1 = fmaf(a.x, w.x, acc1); acc1 = fmaf(a.y, w.y, acc1);
                acc1 = fmaf(a.z, w.z, acc1); acc1 = fmaf(a.w, w.w, acc1);
            }
        }
    }
    zs[r0o][c0o] = acc0 + b3[c0o];
    if (o1 < 440) zs[r1o][c1o] = acc1 + b3[c1o];
    __syncthreads();

    if (t < 48) {
        const int r     = t / 6;
        const int g     = t - 6 * r;
        const int start = (g == 0) ? 0 : 5 + 10 * (g - 1);
        const int len   = (g == 0) ? 5 : 10;
        float m = -3.0e38f;
        for (int c = 0; c < len; ++c) m = fmaxf(m, zs[r][start + c]);
        float s = 0.f;
        for (int c = 0; c < len; ++c) s += __expf(zs[r][start + c] - m);
        const float inv = 1.0f / s;
        float* dst = &g_x3[(size_t)(r0 + r) * 64];
        for (int c = 0; c < len; ++c)
            dst[start + c] = __expf(zs[r][start + c] - m) * inv;
    }
}

// ---------------------------------------------------------------------------
// Kernel B: expansion.  out[b, i] constant over runs of 10 (r = i/10).
// grid (8, 512), 640 threads; loop-invariant per-thread run phase;
// streaming (evict-first) float4 stores.  [R8 form — best measured]
// ---------------------------------------------------------------------------
__global__ void __launch_bounds__(640) expand_kernel(float* __restrict__ out)
{
    __shared__ float p[64];
    __shared__ float sv[1288];

    const unsigned t   = threadIdx.x;
    const unsigned bx  = blockIdx.x;
    const unsigned b   = blockIdx.y;
    const unsigned pad = b & 3u;
    const unsigned rbase = bx * 1280u;   // multiple of 10

    if (t < 64u) p[t] = g_x3[(size_t)b * 64u + t];
    __syncthreads();

    #pragma unroll
    for (unsigned kk = 0; kk < 3u; ++kk) {
        const unsigned ri = t + kk * 640u;
        if (ri < 1282u) {
            const unsigned r = rbase + ri;
            float v = 0.f;
            if (r < 10000u) {
                if (r == 0u) {
                    v = p[0];
                } else if (r < 10u) {
                    v = p[1] * p[5 + r];
                } else if (r < 100u) {
                    const unsigned q1 = r / 10u;
                    v = p[2] * p[5 + q1] * p[15 + (r - 10u * q1)];
                } else if (r < 1000u) {
                    const unsigned q1 = r / 10u, q2 = r / 100u;
                    v = p[3] * p[5 + q2] * p[15 + (q1 - 10u * q2)]
                             * p[25 + (r - 10u * q1)];
                } else {
                    const unsigned q1 = r / 10u, q2 = r / 100u, q3 = r / 1000u;
                    v = p[4] * p[5 + q3] * p[15 + (q2 - 10u * q3)]
                             * p[25 + (q1 - 10u * q2)] * p[35 + (r - 10u * q1)];
                }
            }
            sv[ri] = v;
        }
    }
    __syncthreads();

    float* o = out + (size_t)b * 99999u;
    float4* ov = reinterpret_cast<float4*>(o + pad);   // 16B-aligned

    const unsigned ph  = pad + 4u * t;       // < 2563
    const unsigned rt  = ph / 10u;
    const unsigned rem = ph - 10u * rt;
    const bool c1 = (rem + 1u < 10u);
    const bool c2 = (rem + 2u < 10u);
    const bool c3 = (rem + 3u < 10u);

    if (bx < 7u) {
        unsigned vi = bx * 3200u + t;
        unsigned ri = rt;
        #pragma unroll
        for (int k = 0; k < 5; ++k) {
            const float f0 = sv[ri];
            const float f1 = sv[ri + 1u];
            float4 w;
            w.x = f0;
            w.y = c1 ? f0 : f1;
            w.z = c2 ? f0 : f1;
            w.w = c3 ? f0 : f1;
            __stcs(&ov[vi], w);
            vi += 640u;
            ri += 256u;
        }
        if (bx == 0u) {
            if (t == 0u) o[0] = p[1] * p[5];
            else if (t < pad) o[t] = p[0];   // pad <= 3
        }
    } else {
        unsigned vi = 22400u + t;
        unsigned ri = rt;
        #pragma unroll
        for (int k = 0; k < 5; ++k) {
            if (vi < 24999u) {
                const float f0 = sv[ri];
                const float f1 = sv[ri + 1u];
                float4 w;
                w.x = f0;
                w.y = c1 ? f0 : f1;
                w.z = c2 ? f0 : f1;
                w.w = c3 ? f0 : f1;
                __stcs(&ov[vi], w);
            }
            vi += 640u;
            ri += 256u;
        }
        if (t < 3u - pad) {
            o[pad + 99996u + t] = sv[1039];
        }
    }
}

// ---------------------------------------------------------------------------
extern "C" void kernel_launch(void* const* d_in, const int* in_sizes, int n_in,
                              void* d_out, int out_size)
{
    (void)in_sizes; (void)n_in; (void)out_size;
    const float* x  = (const float*)d_in[0];   // [512, 512]
    const float* w2 = (const float*)d_in[1];   // [256, 512]
    const float* b2 = (const float*)d_in[2];   // [256]
    const float* w3 = (const float*)d_in[3];   // [55, 256]
    const float* b3 = (const float*)d_in[4];   // [55]
    float* out = (float*)d_out;                // [512, 99999]

    gemm1_part_kernel<<<dim3(8, 4, 16), 128>>>(x, w2);
    head_kernel<<<64, 256>>>(b2, w3, b3);
    expand_kernel<<<dim3(8, 512), 640>>>(out);
}

// round 13
// speedup vs baseline: 1.1239x; 1.0426x over previous
#include <cuda_runtime.h>

// Scratch: split-K partials [16][512*256] (8 MB) and x3 [512 x 64].
static __device__ float g_part[16][512 * 256];
static __device__ float g_x3[512 * 64];

// ---------------------------------------------------------------------------
// Kernel A1: split-K partial GEMM.  part[z] = x[32r x 32k] @ w2^T[32k x 64h]
// grid (16, 4, 16) = 1024 blocks, 128 threads, all resident.  [R8 form]
// ---------------------------------------------------------------------------
__global__ void __launch_bounds__(128) gemm1_part_kernel(
    const float* __restrict__ x,    // [512, 512]
    const float* __restrict__ w2)   // [256, 512]
{
    __shared__ float xs[32][36];
    __shared__ float ws[64][36];

    const int t  = threadIdx.x;
    const int r0 = blockIdx.x * 32;
    const int h0 = blockIdx.y * 64;
    const int k0 = blockIdx.z * 32;

    #pragma unroll
    for (int i = 0; i < 2; ++i) {
        const int idx = t + i * 128;
        const int r   = idx >> 3;
        const int kq  = (idx & 7) * 4;
        float4 v = *reinterpret_cast<const float4*>(
            x + (size_t)(r0 + r) * 512 + k0 + kq);
        *reinterpret_cast<float4*>(&xs[r][kq]) = v;
    }
    #pragma unroll
    for (int i = 0; i < 4; ++i) {
        const int idx = t + i * 128;
        const int r   = idx >> 3;
        const int kq  = (idx & 7) * 4;
        float4 v = *reinterpret_cast<const float4*>(
            w2 + (size_t)(h0 + r) * 512 + k0 + kq);
        *reinterpret_cast<float4*>(&ws[r][kq]) = v;
    }

    float acc[4][4];
    #pragma unroll
    for (int i = 0; i < 4; ++i)
        #pragma unroll
        for (int j = 0; j < 4; ++j) acc[i][j] = 0.f;

    const int tx = t & 15;
    const int ty = t >> 4;

    __syncthreads();

    #pragma unroll
    for (int kq = 0; kq < 32; kq += 4) {
        float4 a[4], bv[4];
        #pragma unroll
        for (int i = 0; i < 4; ++i)
            a[i] = *reinterpret_cast<const float4*>(&xs[ty + 8 * i][kq]);
        #pragma unroll
        for (int j = 0; j < 4; ++j)
            bv[j] = *reinterpret_cast<const float4*>(&ws[tx + 16 * j][kq]);
        #pragma unroll
        for (int i = 0; i < 4; ++i)
            #pragma unroll
            for (int j = 0; j < 4; ++j) {
                acc[i][j] = fmaf(a[i].x, bv[j].x, acc[i][j]);
                acc[i][j] = fmaf(a[i].y, bv[j].y, acc[i][j]);
                acc[i][j] = fmaf(a[i].z, bv[j].z, acc[i][j]);
                acc[i][j] = fmaf(a[i].w, bv[j].w, acc[i][j]);
            }
    }

    float* dst = g_part[blockIdx.z];
    #pragma unroll
    for (int i = 0; i < 4; ++i)
        #pragma unroll
        for (int j = 0; j < 4; ++j)
            dst[(size_t)(r0 + ty + 8 * i) * 256 + h0 + tx + 16 * j] = acc[i][j];
}

// ---------------------------------------------------------------------------
// Kernel A2 v3: parallel head.  256 blocks x 256 threads, 2 rows per block.
//   Phase A (t<128): one float4 h-chunk per thread; 16 coalesced independent
//                    LDG.128 partial reads + bias + LeakyReLU -> smem.
//   Phase B (t<220): 110 outputs x 2 half-dots (128-k) each, pair-reduce.
//   Phase C: softmaxes (12 threads) -> g_x3.
// ---------------------------------------------------------------------------
__global__ void __launch_bounds__(256) head_kernel(
    const float* __restrict__ b2,   // [256]
    const float* __restrict__ w3,   // [55, 256]
    const float* __restrict__ b3)   // [55]
{
    __shared__ float hs[2][260];    // 1040B row stride (16B-aligned)
    __shared__ float zp[110][2];
    __shared__ float zs[2][60];

    const int t  = threadIdx.x;
    const int r0 = blockIdx.x * 2;

    // --- Phase A: reduce 16 partials, vectorized ---
    if (t < 128) {
        const int i  = t >> 6;          // row 0/1
        const int cg = t & 63;          // float4 col group
        float4 acc = *reinterpret_cast<const float4*>(b2 + cg * 4);
        const size_t off = (size_t)(r0 + i) * 256 + cg * 4;
        #pragma unroll
        for (int z = 0; z < 16; ++z) {
            const float4 v = *reinterpret_cast<const float4*>(&g_part[z][off]);
            acc.x += v.x; acc.y += v.y; acc.z += v.z; acc.w += v.w;
        }
        acc.x = (acc.x >= 0.f) ? acc.x : 0.01f * acc.x;
        acc.y = (acc.y >= 0.f) ? acc.y : 0.01f * acc.y;
        acc.z = (acc.z >= 0.f) ? acc.z : 0.01f * acc.z;
        acc.w = (acc.w >= 0.f) ? acc.w : 0.01f * acc.w;
        *reinterpret_cast<float4*>(&hs[i][cg * 4]) = acc;
    }
    __syncthreads();

    // --- Phase B: GEMM2 half-dots ---
    if (t < 220) {
        const int o    = t >> 1;        // output 0..109
        const int half = t & 1;
        const int r    = o & 1;
        const int c    = o >> 1;        // 0..54
        const float4* hv = reinterpret_cast<const float4*>(&hs[r][half * 128]);
        const float4* wv = reinterpret_cast<const float4*>(
            w3 + (size_t)c * 256 + half * 128);
        float acc = 0.f;
        #pragma unroll 8
        for (int k = 0; k < 32; ++k) {
            const float4 a = hv[k];
            const float4 w = __ldg(&wv[k]);
            acc = fmaf(a.x, w.x, acc); acc = fmaf(a.y, w.y, acc);
            acc = fmaf(a.z, w.z, acc); acc = fmaf(a.w, w.w, acc);
        }
        zp[o][half] = acc;
    }
    __syncthreads();

    if (t < 110) {
        const int r = t & 1;
        const int c = t >> 1;
        zs[r][c] = zp[t][0] + zp[t][1] + b3[c];
    }
    __syncthreads();

    // --- Phase C: softmaxes, 2 rows x 6 groups ---
    if (t < 12) {
        const int r     = t / 6;
        const int g     = t - 6 * r;
        const int start = (g == 0) ? 0 : 5 + 10 * (g - 1);
        const int len   = (g == 0) ? 5 : 10;
        float m = -3.0e38f;
        for (int c = 0; c < len; ++c) m = fmaxf(m, zs[r][start + c]);
        float s = 0.f;
        for (int c = 0; c < len; ++c) s += __expf(zs[r][start + c] - m);
        const float inv = 1.0f / s;
        float* dst = &g_x3[(size_t)(r0 + r) * 64];
        for (int c = 0; c < len; ++c)
            dst[start + c] = __expf(zs[r][start + c] - m) * inv;
    }
}

// ---------------------------------------------------------------------------
// Kernel B: expansion.  out[b, i] constant over runs of 10 (r = i/10).
// grid (8, 512), 640 threads; loop-invariant per-thread run phase;
// streaming (evict-first) float4 stores.  [R8 form — best measured]
// ---------------------------------------------------------------------------
__global__ void __launch_bounds__(640) expand_kernel(float* __restrict__ out)
{
    __shared__ float p[64];
    __shared__ float sv[1288];

    const unsigned t   = threadIdx.x;
    const unsigned bx  = blockIdx.x;
    const unsigned b   = blockIdx.y;
    const unsigned pad = b & 3u;
    const unsigned rbase = bx * 1280u;   // multiple of 10

    if (t < 64u) p[t] = g_x3[(size_t)b * 64u + t];
    __syncthreads();

    #pragma unroll
    for (unsigned kk = 0; kk < 3u; ++kk) {
        const unsigned ri = t + kk * 640u;
        if (ri < 1282u) {
            const unsigned r = rbase + ri;
            float v = 0.f;
            if (r < 10000u) {
                if (r == 0u) {
                    v = p[0];
                } else if (r < 10u) {
                    v = p[1] * p[5 + r];
                } else if (r < 100u) {
                    const unsigned q1 = r / 10u;
                    v = p[2] * p[5 + q1] * p[15 + (r - 10u * q1)];
                } else if (r < 1000u) {
                    const unsigned q1 = r / 10u, q2 = r / 100u;
                    v = p[3] * p[5 + q2] * p[15 + (q1 - 10u * q2)]
                             * p[25 + (r - 10u * q1)];
                } else {
                    const unsigned q1 = r / 10u, q2 = r / 100u, q3 = r / 1000u;
                    v = p[4] * p[5 + q3] * p[15 + (q2 - 10u * q3)]
                             * p[25 + (q1 - 10u * q2)] * p[35 + (r - 10u * q1)];
                }
            }
            sv[ri] = v;
        }
    }
    __syncthreads();

    float* o = out + (size_t)b * 99999u;
    float4* ov = reinterpret_cast<float4*>(o + pad);   // 16B-aligned

    const unsigned ph  = pad + 4u * t;       // < 2563
    const unsigned rt  = ph / 10u;
    const unsigned rem = ph - 10u * rt;
    const bool c1 = (rem + 1u < 10u);
    const bool c2 = (rem + 2u < 10u);
    const bool c3 = (rem + 3u < 10u);

    if (bx < 7u) {
        unsigned vi = bx * 3200u + t;
        unsigned ri = rt;
        #pragma unroll
        for (int k = 0; k < 5; ++k) {
            const float f0 = sv[ri];
            const float f1 = sv[ri + 1u];
            float4 w;
            w.x = f0;
            w.y = c1 ? f0 : f1;
            w.z = c2 ? f0 : f1;
            w.w = c3 ? f0 : f1;
            __stcs(&ov[vi], w);
            vi += 640u;
            ri += 256u;
        }
        if (bx == 0u) {
            if (t == 0u) o[0] = p[1] * p[5];
            else if (t < pad) o[t] = p[0];   // pad <= 3
        }
    } else {
        unsigned vi = 22400u + t;
        unsigned ri = rt;
        #pragma unroll
        for (int k = 0; k < 5; ++k) {
            if (vi < 24999u) {
                const float f0 = sv[ri];
                const float f1 = sv[ri + 1u];
                float4 w;
                w.x = f0;
                w.y = c1 ? f0 : f1;
                w.z = c2 ? f0 : f1;
                w.w = c3 ? f0 : f1;
                __stcs(&ov[vi], w);
            }
            vi += 640u;
            ri += 256u;
        }
        if (t < 3u - pad) {
            o[pad + 99996u + t] = sv[1039];
        }
    }
}

// ---------------------------------------------------------------------------
extern "C" void kernel_launch(void* const* d_in, const int* in_sizes, int n_in,
                              void* d_out, int out_size)
{
    (void)in_sizes; (void)n_in; (void)out_size;
    const float* x  = (const float*)d_in[0];   // [512, 512]
    const float* w2 = (const float*)d_in[1];   // [256, 512]
    const float* b2 = (const float*)d_in[2];   // [256]
    const float* w3 = (const float*)d_in[3];   // [55, 256]
    const float* b3 = (const float*)d_in[4];   // [55]
    float* out = (float*)d_out;                // [512, 99999]

    gemm1_part_kernel<<<dim3(16, 4, 16), 128>>>(x, w2);
    head_kernel<<<256, 256>>>(b2, w3, b3);
    expand_kernel<<<dim3(8, 512), 640>>>(out);
}